// round 11
// baseline (speedup 1.0000x reference)
#include <cuda_runtime.h>

// MotionProjector:
//   out[b,c,v] = sum_{k<7} mask[b,k,v] * (A_bk · g(v) + bvec_bk)_c
//   A = R - I, bvec = t + p - R p, p = weighted centroid of mask over grid.
// grids == meshgrid(linspace(-1,1,64)^3), computed analytically from the index.
//
// 3 launches:
//   reduce_kernel : grid (64, 4)  — per block: one 1024-float4 voxel chunk,
//                   ALL 7 k slices at once (28 independent loads/thread).
//   coeff_kernel  : 1 block, 28 warps — fold partials, build affine coeffs.
//   motion_kernel : grid (128, 4) — 2 float4/thread, 14-way load MLP,
//                   coeffs staged to smem with a trivial 84-float preamble.

namespace {
constexpr int Sd   = 64;
constexpr int VOX  = Sd * Sd * Sd;       // 262144
constexpr int V4   = VOX / 4;            // 65536 float4 per (b,k) slice
constexpr int Bn   = 4;
constexpr int KM   = 7;                  // k = K-1 contributes exactly zero
constexpr int NBK  = Bn * KM;            // 28
constexpr int CHK  = 64;                 // voxel chunks per b in pass 1
}

// partials[(b*KM + k)*CHK + chunk] = (s, sx, sy, sz)
__device__ float4 g_partials[NBK * CHK];
__device__ float  g_coeffs[NBK * 12];    // per (b,k): A row-major [0..8], bvec [9..11]

__device__ __forceinline__ float coordf(int idx) {
    return fmaf((float)idx, 2.0f / 63.0f, -1.0f);
}

// ---------------------------------------------------------------------------
// Pass 1: per-(b,chunk) block reduces all 7 k slices at once.
// ---------------------------------------------------------------------------
__global__ void __launch_bounds__(256, 2)
reduce_kernel(const float* __restrict__ mask) {
    const int t     = threadIdx.x;
    const int chunk = blockIdx.x;            // 0..63
    const int b     = blockIdx.y;            // 0..3
    const float4* __restrict__ mb =
        reinterpret_cast<const float4*>(mask) + (size_t)b * 8 * V4 +
        (size_t)chunk * 1024;

    float s[KM], sx[KM], sy[KM], sz[KM];
#pragma unroll
    for (int k = 0; k < KM; ++k) { s[k] = sx[k] = sy[k] = sz[k] = 0.f; }

#pragma unroll
    for (int r = 0; r < 4; ++r) {
        const int q = r * 256 + t;           // float4 index within chunk
        const int v = (chunk * 1024 + q) << 2;
        const float gx  = coordf(v >> 12);
        const float gy  = coordf((v >> 6) & 63);
        const int   l   = v & 63;
        const float gz0 = coordf(l),     gz1 = coordf(l + 1);
        const float gz2 = coordf(l + 2), gz3 = coordf(l + 3);
#pragma unroll
        for (int k = 0; k < KM; ++k) {
            const float4 mv = mb[(size_t)k * V4 + q];
            const float ms = (mv.x + mv.y) + (mv.z + mv.w);
            s[k]  += ms;
            sx[k]  = fmaf(ms, gx, sx[k]);
            sy[k]  = fmaf(ms, gy, sy[k]);
            sz[k]  = fmaf(mv.x, gz0, fmaf(mv.y, gz1,
                     fmaf(mv.z, gz2, fmaf(mv.w, gz3, sz[k]))));
        }
    }

#pragma unroll
    for (int o = 16; o > 0; o >>= 1) {
#pragma unroll
        for (int k = 0; k < KM; ++k) {
            s[k]  += __shfl_down_sync(0xffffffffu, s[k],  o);
            sx[k] += __shfl_down_sync(0xffffffffu, sx[k], o);
            sy[k] += __shfl_down_sync(0xffffffffu, sy[k], o);
            sz[k] += __shfl_down_sync(0xffffffffu, sz[k], o);
        }
    }
    __shared__ float4 red[8][KM];
    const int w = t >> 5, lane = t & 31;
    if (lane == 0) {
#pragma unroll
        for (int k = 0; k < KM; ++k)
            red[w][k] = make_float4(s[k], sx[k], sy[k], sz[k]);
    }
    __syncthreads();
    if (t < KM) {
        float4 a = red[0][t];
#pragma unroll
        for (int ww = 1; ww < 8; ++ww) {
            const float4 p = red[ww][t];
            a.x += p.x; a.y += p.y; a.z += p.z; a.w += p.w;
        }
        g_partials[(b * KM + t) * CHK + chunk] = a;
    }
}

// ---------------------------------------------------------------------------
// Pass 2: one warp per (b,k) folds 64 partials -> pivot -> affine coeffs.
// 1 block, 28 warps (896 threads). Fixed-order sums => deterministic.
// ---------------------------------------------------------------------------
__global__ void __launch_bounds__(NBK * 32)
coeff_kernel(const float* __restrict__ trans, const float* __restrict__ rot) {
    const int w = threadIdx.x >> 5, lane = threadIdx.x & 31;
    const float4* __restrict__ gp = g_partials + w * CHK;
    const float4 p0 = gp[2 * lane];
    const float4 p1 = gp[2 * lane + 1];
    float s  = p0.x + p1.x, sx = p0.y + p1.y;
    float sy = p0.z + p1.z, sz = p0.w + p1.w;
#pragma unroll
    for (int o = 16; o > 0; o >>= 1) {
        s  += __shfl_down_sync(0xffffffffu, s,  o);
        sx += __shfl_down_sync(0xffffffffu, sx, o);
        sy += __shfl_down_sync(0xffffffffu, sy, o);
        sz += __shfl_down_sync(0xffffffffu, sz, o);
    }
    if (lane == 0) {
        const float px = sx / s, py = sy / s, pz = sz / s;
        const float pv[3] = {px, py, pz};
        const float* __restrict__ R = rot   + (size_t)w * 9;
        const float* __restrict__ T = trans + (size_t)w * 3;
        float* __restrict__ C = g_coeffs + w * 12;
#pragma unroll
        for (int r = 0; r < 3; ++r) {
            const float r0 = R[r * 3 + 0], r1 = R[r * 3 + 1], r2 = R[r * 3 + 2];
            C[r * 3 + 0] = r0 - (r == 0 ? 1.f : 0.f);
            C[r * 3 + 1] = r1 - (r == 1 ? 1.f : 0.f);
            C[r * 3 + 2] = r2 - (r == 2 ? 1.f : 0.f);
            C[9 + r]     = T[r] + pv[r] - (r0 * px + r1 * py + r2 * pz);
        }
    }
}

// ---------------------------------------------------------------------------
// Pass 3: apply motion. 2 float4 per thread (14-way load MLP).
// grid (V4/512, 4), 256 threads.
// ---------------------------------------------------------------------------
__global__ void __launch_bounds__(256)
motion_kernel(const float* __restrict__ mask, float* __restrict__ out) {
    const int t = threadIdx.x;
    const int b = blockIdx.y;
    __shared__ float sc[KM * 12];
    if (t < KM * 12) sc[t] = g_coeffs[b * KM * 12 + t];
    __syncthreads();

    const int q0 = blockIdx.x * 512 + t;     // float4 indices q0, q0+256
    const int q1 = q0 + 256;

    const int v0 = q0 << 2, v1 = q1 << 2;
    const float gx0  = coordf(v0 >> 12),        gx1  = coordf(v1 >> 12);
    const float gy0  = coordf((v0 >> 6) & 63),  gy1  = coordf((v1 >> 6) & 63);
    const int   l0   = v0 & 63,                 l1   = v1 & 63;
    const float gz00 = coordf(l0),     gz01 = coordf(l0 + 1);
    const float gz02 = coordf(l0 + 2), gz03 = coordf(l0 + 3);
    const float gz10 = coordf(l1),     gz11 = coordf(l1 + 1);
    const float gz12 = coordf(l1 + 2), gz13 = coordf(l1 + 3);

    float4 a0 = make_float4(0.f, 0.f, 0.f, 0.f);
    float4 a1 = make_float4(0.f, 0.f, 0.f, 0.f);
    float4 a2 = make_float4(0.f, 0.f, 0.f, 0.f);
    float4 c0 = make_float4(0.f, 0.f, 0.f, 0.f);
    float4 c1 = make_float4(0.f, 0.f, 0.f, 0.f);
    float4 c2 = make_float4(0.f, 0.f, 0.f, 0.f);

    const float4* __restrict__ mb =
        reinterpret_cast<const float4*>(mask) + (size_t)b * 8 * V4;

#pragma unroll
    for (int k = 0; k < KM; ++k) {
        const float4 m0 = mb[(size_t)k * V4 + q0];
        const float4 m1 = mb[(size_t)k * V4 + q1];
        const float* __restrict__ C = sc + k * 12;
        // c = 0
        {
            const float A0 = C[0], A1 = C[1], A2 = C[2], Bv = C[9];
            const float com0 = fmaf(A0, gx0, fmaf(A1, gy0, Bv));
            const float com1 = fmaf(A0, gx1, fmaf(A1, gy1, Bv));
            a0.x = fmaf(m0.x, fmaf(A2, gz00, com0), a0.x);
            a0.y = fmaf(m0.y, fmaf(A2, gz01, com0), a0.y);
            a0.z = fmaf(m0.z, fmaf(A2, gz02, com0), a0.z);
            a0.w = fmaf(m0.w, fmaf(A2, gz03, com0), a0.w);
            c0.x = fmaf(m1.x, fmaf(A2, gz10, com1), c0.x);
            c0.y = fmaf(m1.y, fmaf(A2, gz11, com1), c0.y);
            c0.z = fmaf(m1.z, fmaf(A2, gz12, com1), c0.z);
            c0.w = fmaf(m1.w, fmaf(A2, gz13, com1), c0.w);
        }
        // c = 1
        {
            const float A0 = C[3], A1 = C[4], A2 = C[5], Bv = C[10];
            const float com0 = fmaf(A0, gx0, fmaf(A1, gy0, Bv));
            const float com1 = fmaf(A0, gx1, fmaf(A1, gy1, Bv));
            a1.x = fmaf(m0.x, fmaf(A2, gz00, com0), a1.x);
            a1.y = fmaf(m0.y, fmaf(A2, gz01, com0), a1.y);
            a1.z = fmaf(m0.z, fmaf(A2, gz02, com0), a1.z);
            a1.w = fmaf(m0.w, fmaf(A2, gz03, com0), a1.w);
            c1.x = fmaf(m1.x, fmaf(A2, gz10, com1), c1.x);
            c1.y = fmaf(m1.y, fmaf(A2, gz11, com1), c1.y);
            c1.z = fmaf(m1.z, fmaf(A2, gz12, com1), c1.z);
            c1.w = fmaf(m1.w, fmaf(A2, gz13, com1), c1.w);
        }
        // c = 2
        {
            const float A0 = C[6], A1 = C[7], A2 = C[8], Bv = C[11];
            const float com0 = fmaf(A0, gx0, fmaf(A1, gy0, Bv));
            const float com1 = fmaf(A0, gx1, fmaf(A1, gy1, Bv));
            a2.x = fmaf(m0.x, fmaf(A2, gz00, com0), a2.x);
            a2.y = fmaf(m0.y, fmaf(A2, gz01, com0), a2.y);
            a2.z = fmaf(m0.z, fmaf(A2, gz02, com0), a2.z);
            a2.w = fmaf(m0.w, fmaf(A2, gz03, com0), a2.w);
            c2.x = fmaf(m1.x, fmaf(A2, gz10, com1), c2.x);
            c2.y = fmaf(m1.y, fmaf(A2, gz11, com1), c2.y);
            c2.z = fmaf(m1.z, fmaf(A2, gz12, com1), c2.z);
            c2.w = fmaf(m1.w, fmaf(A2, gz13, com1), c2.w);
        }
    }

    float4* __restrict__ ob = reinterpret_cast<float4*>(out);
    ob[(size_t)(b * 3 + 0) * V4 + q0] = a0;
    ob[(size_t)(b * 3 + 0) * V4 + q1] = c0;
    ob[(size_t)(b * 3 + 1) * V4 + q0] = a1;
    ob[(size_t)(b * 3 + 1) * V4 + q1] = c1;
    ob[(size_t)(b * 3 + 2) * V4 + q0] = a2;
    ob[(size_t)(b * 3 + 2) * V4 + q1] = c2;
}

// ---------------------------------------------------------------------------
extern "C" void kernel_launch(void* const* d_in, const int* in_sizes, int n_in,
                              void* d_out, int out_size) {
    const float* mask  = (const float*)d_in[0];   // (4, 8, 64, 64, 64)
    const float* trans = (const float*)d_in[1];   // (4, 7, 3)
    const float* rot   = (const float*)d_in[2];   // (4, 7, 3, 3)
    // d_in[3] = grids — recomputed analytically, never read.
    float* out = (float*)d_out;                   // (4, 3, 64, 64, 64)

    reduce_kernel<<<dim3(CHK, Bn), 256>>>(mask);
    coeff_kernel<<<1, NBK * 32>>>(trans, rot);
    motion_kernel<<<dim3(V4 / 512, Bn), 256>>>(mask, out);
}